// round 4
// baseline (speedup 1.0000x reference)
#include <cuda_runtime.h>
#include <math.h>

#define EMBED   1024
#define NHEADS  16
#define HD      64
#define SEQ     2048
#define BATCH   2
#define TOKENS  (BATCH * SEQ)      /* 4096 */
#define QKVN    (3 * EMBED)        /* 3072 */

// Scratch: qkv projection output [TOKENS, 3*EMBED] (48 MB) and
// attention output in token-major layout [TOKENS, EMBED] (16 MB).
__device__ __align__(256) float g_qkv[(size_t)TOKENS * QKVN];
__device__ __align__(256) float g_attn[(size_t)TOKENS * EMBED];

// ---------------------------------------------------------------------------
// SGEMM + bias: C[M,N] = A[M,K] @ B[K,N] + bias[N]
// Block tile 128x128, K-step 16, 256 threads, 8x8 register micro-tile.
// All dims used here are multiples of the tile sizes -> no bounds checks.
// ---------------------------------------------------------------------------
__global__ __launch_bounds__(256) void sgemm_bias_kernel(
    const float* __restrict__ A, const float* __restrict__ B,
    const float* __restrict__ bias, float* __restrict__ C,
    int M, int N, int K)
{
    __shared__ float As[16][128];   // transposed A tile: As[k][m]
    __shared__ float Bs[16][128];   // Bs[k][n]

    const int tid = threadIdx.x;
    const int tx = tid & 15;        // column group 0..15
    const int ty = tid >> 4;        // row group 0..15
    const int bm = blockIdx.y * 128;
    const int bn = blockIdx.x * 128;

    float acc[8][8];
#pragma unroll
    for (int i = 0; i < 8; i++)
#pragma unroll
        for (int j = 0; j < 8; j++) acc[i][j] = 0.f;

    const float* Ab = A + (size_t)bm * K;
    const float* Bb = B + bn;

    for (int k0 = 0; k0 < K; k0 += 16) {
        __syncthreads();
        // Load A tile 128x16 (float4 along K), store transposed.
#pragma unroll
        for (int l = 0; l < 2; l++) {
            int id  = tid + l * 256;        // 0..511
            int row = id >> 2;              // 0..127
            int kq  = (id & 3) << 2;        // 0,4,8,12
            float4 a4 = *(const float4*)(Ab + (size_t)row * K + k0 + kq);
            As[kq + 0][row] = a4.x;
            As[kq + 1][row] = a4.y;
            As[kq + 2][row] = a4.z;
            As[kq + 3][row] = a4.w;
        }
        // Load B tile 16x128 (float4 along N).
#pragma unroll
        for (int l = 0; l < 2; l++) {
            int id  = tid + l * 256;
            int row = id >> 5;              // 0..15
            int nq  = (id & 31) << 2;       // 0..124
            *(float4*)(&Bs[row][nq]) =
                *(const float4*)(Bb + (size_t)(k0 + row) * N + nq);
        }
        __syncthreads();

#pragma unroll
        for (int k = 0; k < 16; k++) {
            float ra[8], rb[8];
#pragma unroll
            for (int i = 0; i < 8; i++) ra[i] = As[k][ty * 8 + i];
#pragma unroll
            for (int j = 0; j < 8; j++) rb[j] = Bs[k][tx * 8 + j];
#pragma unroll
            for (int i = 0; i < 8; i++)
#pragma unroll
                for (int j = 0; j < 8; j++)
                    acc[i][j] = fmaf(ra[i], rb[j], acc[i][j]);
        }
    }

    // Epilogue: add bias, vectorized stores.
#pragma unroll
    for (int i = 0; i < 8; i++) {
        size_t row = (size_t)(bm + ty * 8 + i);
#pragma unroll
        for (int j4 = 0; j4 < 2; j4++) {
            int col = bn + tx * 8 + j4 * 4;
            float4 o;
            o.x = acc[i][j4 * 4 + 0] + bias[col + 0];
            o.y = acc[i][j4 * 4 + 1] + bias[col + 1];
            o.z = acc[i][j4 * 4 + 2] + bias[col + 2];
            o.w = acc[i][j4 * 4 + 3] + bias[col + 3];
            *(float4*)(C + row * N + col) = o;
        }
    }
}

// ---------------------------------------------------------------------------
// Flash attention, fp32. One CTA per (b, h, 64-row q tile).
// 256 threads: ty = tid/16 -> 4 q-rows each; tx = tid%16 -> column lanes.
// KV tiles of 32 rows. Online softmax. Output written token-major so the
// final GEMM reads a plain [TOKENS, EMBED] matrix.
// Shared tiles padded (stride 65 / 33) for conflict-free access.
// Total smem = 41.75 KB (static, under the 48 KB cap).
// ---------------------------------------------------------------------------
__global__ __launch_bounds__(256) void flash_attn_kernel(
    const float* __restrict__ qkv, float* __restrict__ attn_out)
{
    __shared__ float Qs[64][65];
    __shared__ float Ks[32][65];
    __shared__ float Vs[32][65];
    __shared__ float Ps[64][33];

    const int tid = threadIdx.x;
    const int tx = tid & 15;
    const int ty = tid >> 4;
    const int h  = blockIdx.y;
    const int b  = blockIdx.z;
    const int n0 = blockIdx.x * 64;

    // qkv row layout: [token][3*EMBED]; q at col h*64, k at 1024+h*64, v at 2048+h*64
    const float* base = qkv + (size_t)b * SEQ * QKVN + h * HD;

    // Load Q tile 64x64 (coalesced float4 rows).
#pragma unroll
    for (int l = 0; l < 4; l++) {
        int id = tid + l * 256;         // 0..1023
        int r  = id >> 4;               // 0..63
        int d4 = (id & 15) << 2;        // 0..60
        float4 q4 = *(const float4*)(base + (size_t)(n0 + r) * QKVN + d4);
        Qs[r][d4 + 0] = q4.x; Qs[r][d4 + 1] = q4.y;
        Qs[r][d4 + 2] = q4.z; Qs[r][d4 + 3] = q4.w;
    }

    float mrow[4], lrow[4], o[4][4];
#pragma unroll
    for (int i = 0; i < 4; i++) {
        mrow[i] = -1e30f;
        lrow[i] = 0.f;
#pragma unroll
        for (int ii = 0; ii < 4; ii++) o[i][ii] = 0.f;
    }
    const float scale = 0.125f;   // 1/sqrt(64)

    for (int t0 = 0; t0 < SEQ; t0 += 32) {
        __syncthreads();   // prev iter's reads of Ks/Vs/Ps complete
        // Load K and V tiles (32x64 each).
#pragma unroll
        for (int l = 0; l < 2; l++) {
            int id = tid + l * 256;     // 0..511
            int r  = id >> 4;           // 0..31
            int d4 = (id & 15) << 2;
            float4 k4 = *(const float4*)(base + EMBED     + (size_t)(t0 + r) * QKVN + d4);
            float4 v4 = *(const float4*)(base + 2 * EMBED + (size_t)(t0 + r) * QKVN + d4);
            Ks[r][d4 + 0] = k4.x; Ks[r][d4 + 1] = k4.y;
            Ks[r][d4 + 2] = k4.z; Ks[r][d4 + 3] = k4.w;
            Vs[r][d4 + 0] = v4.x; Vs[r][d4 + 1] = v4.y;
            Vs[r][d4 + 2] = v4.z; Vs[r][d4 + 3] = v4.w;
        }
        __syncthreads();

        // S = Q @ K^T for this tile. Thread covers rows ty*4+i, cols {tx, tx+16}.
        float s[4][2];
#pragma unroll
        for (int i = 0; i < 4; i++) { s[i][0] = 0.f; s[i][1] = 0.f; }
#pragma unroll 8
        for (int d = 0; d < 64; d++) {
            float rk0 = Ks[tx][d];
            float rk1 = Ks[tx + 16][d];
#pragma unroll
            for (int i = 0; i < 4; i++) {
                float rq = Qs[ty * 4 + i][d];
                s[i][0] = fmaf(rq, rk0, s[i][0]);
                s[i][1] = fmaf(rq, rk1, s[i][1]);
            }
        }

        // Online softmax update (row group = 16 contiguous lanes in warp).
#pragma unroll
        for (int i = 0; i < 4; i++) {
            float s0 = s[i][0] * scale;
            float s1 = s[i][1] * scale;
            float smax = fmaxf(s0, s1);
#pragma unroll
            for (int msk = 8; msk >= 1; msk >>= 1)
                smax = fmaxf(smax, __shfl_xor_sync(0xffffffffu, smax, msk));
            float mnew = fmaxf(mrow[i], smax);
            float corr = __expf(mrow[i] - mnew);
            float p0 = __expf(s0 - mnew);
            float p1 = __expf(s1 - mnew);
            float ls = p0 + p1;
#pragma unroll
            for (int msk = 8; msk >= 1; msk >>= 1)
                ls += __shfl_xor_sync(0xffffffffu, ls, msk);
            lrow[i] = lrow[i] * corr + ls;
            mrow[i] = mnew;
#pragma unroll
            for (int ii = 0; ii < 4; ii++) o[i][ii] *= corr;
            Ps[ty * 4 + i][tx]      = p0;
            Ps[ty * 4 + i][tx + 16] = p1;
        }
        __syncthreads();

        // O += P @ V. Thread accumulates rows ty*4+i, d-cols {tx + 16*ii}.
#pragma unroll 8
        for (int j = 0; j < 32; j++) {
            float rv[4];
#pragma unroll
            for (int ii = 0; ii < 4; ii++) rv[ii] = Vs[j][tx + 16 * ii];
#pragma unroll
            for (int i = 0; i < 4; i++) {
                float rp = Ps[ty * 4 + i][j];
#pragma unroll
                for (int ii = 0; ii < 4; ii++)
                    o[i][ii] = fmaf(rp, rv[ii], o[i][ii]);
            }
        }
    }

    // Finalize and write token-major: attn_out[token][h*64 + d].
#pragma unroll
    for (int i = 0; i < 4; i++) {
        float inv = 1.f / lrow[i];
        size_t tok = (size_t)b * SEQ + n0 + ty * 4 + i;
#pragma unroll
        for (int ii = 0; ii < 4; ii++)
            attn_out[tok * EMBED + h * HD + tx + 16 * ii] = o[i][ii] * inv;
    }
}

// ---------------------------------------------------------------------------
// Launch: qkv GEMM -> flash attention -> output GEMM. Graph-capturable:
// three kernel launches, no sync, no allocation.
// ---------------------------------------------------------------------------
extern "C" void kernel_launch(void* const* d_in, const int* in_sizes, int n_in,
                              void* d_out, int out_size)
{
    (void)in_sizes; (void)n_in; (void)out_size;
    const float* x     = (const float*)d_in[0];
    const float* w_qkv = (const float*)d_in[1];
    const float* b_qkv = (const float*)d_in[2];
    const float* w_out = (const float*)d_in[3];
    const float* b_out = (const float*)d_in[4];
    float* out = (float*)d_out;

    float* qkv  = nullptr;
    float* attn = nullptr;
    cudaGetSymbolAddress((void**)&qkv,  g_qkv);
    cudaGetSymbolAddress((void**)&attn, g_attn);

    dim3 blk(256);
    // QKV projection: [4096,1024] @ [1024,3072] + b
    sgemm_bias_kernel<<<dim3(QKVN / 128, TOKENS / 128), blk>>>(
        x, w_qkv, b_qkv, qkv, TOKENS, QKVN, EMBED);
    // Attention per (b, h, q-tile)
    flash_attn_kernel<<<dim3(SEQ / 64, NHEADS, BATCH), blk>>>(qkv, attn);
    // Output projection: [4096,1024] @ [1024,1024] + b
    sgemm_bias_kernel<<<dim3(EMBED / 128, TOKENS / 128), blk>>>(
        attn, w_out, b_out, out, TOKENS, EMBED, EMBED);
}

// round 7
// speedup vs baseline: 1.1677x; 1.1677x over previous
#include <cuda_runtime.h>
#include <cstdint>
#include <math.h>

#define EMBED   1024
#define NHEADS  16
#define HD      64
#define SEQ     2048
#define BATCH   2
#define TOKENS  (BATCH * SEQ)      /* 4096 */
#define QKVN    (3 * EMBED)        /* 3072 */

// Scratch (no allocations allowed).
__device__ __align__(256) float g_qkv  [(size_t)TOKENS * QKVN];
__device__ __align__(256) float g_attn [(size_t)TOKENS * EMBED];
__device__ __align__(256) float g_wqkvT[(size_t)QKVN   * EMBED];
__device__ __align__(256) float g_woutT[(size_t)EMBED  * EMBED];

// ===========================================================================
// tf32 mma.sync helpers (baseline PTX, valid on compute_103 non-'a')
// ===========================================================================
__device__ __forceinline__ void mma_tf32(float* d, const uint32_t* a, const uint32_t* b) {
    asm volatile(
        "mma.sync.aligned.m16n8k8.row.col.f32.tf32.tf32.f32 "
        "{%0,%1,%2,%3}, {%4,%5,%6,%7}, {%8,%9}, {%0,%1,%2,%3};\n"
        : "+f"(d[0]), "+f"(d[1]), "+f"(d[2]), "+f"(d[3])
        : "r"(a[0]), "r"(a[1]), "r"(a[2]), "r"(a[3]), "r"(b[0]), "r"(b[1]));
}
__device__ __forceinline__ float tf32_hi(float x) {
    return __uint_as_float(__float_as_uint(x) & 0xFFFFE000u);
}

// ===========================================================================
// Transpose: out[C][R] = in[R][C]  (32x32 tiles, block 32x8)
// ===========================================================================
__global__ __launch_bounds__(256) void transpose_kernel(
    const float* __restrict__ in, float* __restrict__ out, int R, int Ccols)
{
    __shared__ float t[32][33];
    int bx = blockIdx.x * 32, by = blockIdx.y * 32;
#pragma unroll
    for (int i = 0; i < 32; i += 8)
        t[threadIdx.y + i][threadIdx.x] =
            in[(size_t)(by + threadIdx.y + i) * Ccols + bx + threadIdx.x];
    __syncthreads();
#pragma unroll
    for (int i = 0; i < 32; i += 8)
        out[(size_t)(bx + threadIdx.y + i) * R + by + threadIdx.x] =
            t[threadIdx.x][threadIdx.y + i];
}

// ===========================================================================
// Tensor-core GEMM + bias via mma.sync tf32 with 3xTF32 split:
//   C[M,N] = A[M,K] @ Bt[N,K]^T + bias[N]
// Block 128x128, K-chunk 32, 8 warps (warp tile 64x32), two smem stages.
// Smem tiles stored [row][k] with stride 36 floats -> conflict-free fragment
// gathers: bank = (4*gid + tig) % 32 covers all 32 banks exactly once.
// Per stage: Ahi|Alo|Bhi|Blo, each 128*36 floats. Total 2*18432*4 = 147456 B.
// ===========================================================================
#define LDT     36
#define TILE_F  (128 * LDT)          /* 4608 floats */
#define STAGE_F (4 * TILE_F)         /* 18432 floats */
#define GEMM_SMEM_BYTES (2 * STAGE_F * 4)

__global__ __launch_bounds__(256, 1)
void mma_gemm_bias(const float* __restrict__ A, const float* __restrict__ Bt,
                   const float* __restrict__ bias, float* __restrict__ C,
                   int N, int K)
{
    extern __shared__ float sm[];
    const int tid  = threadIdx.x;
    const int wid  = tid >> 5, lane = tid & 31;
    const int gid  = lane >> 2, tig = lane & 3;
    const int wm   = wid & 1, wn = wid >> 1;   // warp grid 2(M) x 4(N)
    const int bm   = blockIdx.y * 128, bn = blockIdx.x * 128;

    float acc[4][4][4];
#pragma unroll
    for (int mi = 0; mi < 4; mi++)
#pragma unroll
        for (int ni = 0; ni < 4; ni++)
#pragma unroll
            for (int r = 0; r < 4; r++) acc[mi][ni][r] = 0.f;

    const float* Ag = A  + (size_t)bm * K;
    const float* Bg = Bt + (size_t)bn * K;

    // Per-thread global-load coords: 4 float4 each for A and B per chunk.
    int grow[4], gc4[4];
#pragma unroll
    for (int p = 0; p < 4; p++) {
        int id = tid + p * 256;       // 0..1023
        grow[p] = id >> 3;            // 0..127
        gc4[p]  = (id & 7) << 2;      // 0,4,..,28
    }

    float4 pa[4], pb[4];
    auto gload = [&](int k0) {
#pragma unroll
        for (int p = 0; p < 4; p++) {
            pa[p] = *(const float4*)(Ag + (size_t)grow[p] * K + k0 + gc4[p]);
            pb[p] = *(const float4*)(Bg + (size_t)grow[p] * K + k0 + gc4[p]);
        }
    };
    auto sts = [&](int st) {
        float* base = sm + st * STAGE_F;
#pragma unroll
        for (int p = 0; p < 4; p++) {
            int off = grow[p] * LDT + gc4[p];
            float4 hi, lo;
            hi.x = tf32_hi(pa[p].x); lo.x = tf32_hi(pa[p].x - hi.x);
            hi.y = tf32_hi(pa[p].y); lo.y = tf32_hi(pa[p].y - hi.y);
            hi.z = tf32_hi(pa[p].z); lo.z = tf32_hi(pa[p].z - hi.z);
            hi.w = tf32_hi(pa[p].w); lo.w = tf32_hi(pa[p].w - hi.w);
            *(float4*)(base + off)          = hi;
            *(float4*)(base + TILE_F + off) = lo;
            hi.x = tf32_hi(pb[p].x); lo.x = tf32_hi(pb[p].x - hi.x);
            hi.y = tf32_hi(pb[p].y); lo.y = tf32_hi(pb[p].y - hi.y);
            hi.z = tf32_hi(pb[p].z); lo.z = tf32_hi(pb[p].z - hi.z);
            hi.w = tf32_hi(pb[p].w); lo.w = tf32_hi(pb[p].w - hi.w);
            *(float4*)(base + 2 * TILE_F + off) = hi;
            *(float4*)(base + 3 * TILE_F + off) = lo;
        }
    };
    auto compute = [&](int st) {
        const float* Ah = sm + st * STAGE_F;
        const float* Al = Ah + TILE_F;
        const float* Bh = Ah + 2 * TILE_F;
        const float* Bl = Ah + 3 * TILE_F;
#pragma unroll
        for (int ks = 0; ks < 4; ks++) {
            const int c0 = ks * 8 + tig;
            uint32_t ahf[4][4], alf[4][4];
#pragma unroll
            for (int mi = 0; mi < 4; mi++) {
                int r0 = (wm * 64 + mi * 16 + gid) * LDT;
                ahf[mi][0] = __float_as_uint(Ah[r0 + c0]);
                ahf[mi][1] = __float_as_uint(Ah[r0 + 8 * LDT + c0]);
                ahf[mi][2] = __float_as_uint(Ah[r0 + c0 + 4]);
                ahf[mi][3] = __float_as_uint(Ah[r0 + 8 * LDT + c0 + 4]);
                alf[mi][0] = __float_as_uint(Al[r0 + c0]);
                alf[mi][1] = __float_as_uint(Al[r0 + 8 * LDT + c0]);
                alf[mi][2] = __float_as_uint(Al[r0 + c0 + 4]);
                alf[mi][3] = __float_as_uint(Al[r0 + 8 * LDT + c0 + 4]);
            }
            uint32_t bhf[4][2], blf[4][2];
#pragma unroll
            for (int ni = 0; ni < 4; ni++) {
                int n0 = (wn * 32 + ni * 8 + gid) * LDT;
                bhf[ni][0] = __float_as_uint(Bh[n0 + c0]);
                bhf[ni][1] = __float_as_uint(Bh[n0 + c0 + 4]);
                blf[ni][0] = __float_as_uint(Bl[n0 + c0]);
                blf[ni][1] = __float_as_uint(Bl[n0 + c0 + 4]);
            }
#pragma unroll
            for (int mi = 0; mi < 4; mi++)
#pragma unroll
                for (int ni = 0; ni < 4; ni++) {
                    mma_tf32(acc[mi][ni], ahf[mi], bhf[ni]);
                    mma_tf32(acc[mi][ni], ahf[mi], blf[ni]);
                    mma_tf32(acc[mi][ni], alf[mi], bhf[ni]);
                }
        }
    };

    const int NCH = K >> 5;
    gload(0);
    sts(0);
    __syncthreads();
    for (int c = 0; c < NCH; c++) {
        const int st = c & 1;
        if (c + 1 < NCH) gload((c + 1) * 32);
        compute(st);
        __syncthreads();
        if (c + 1 < NCH) {
            sts(st ^ 1);
            __syncthreads();
        }
    }

    // Epilogue: bias + float2 stores straight from accumulators.
#pragma unroll
    for (int mi = 0; mi < 4; mi++) {
        int row = bm + wm * 64 + mi * 16 + gid;
#pragma unroll
        for (int ni = 0; ni < 4; ni++) {
            int col = bn + wn * 32 + ni * 8 + 2 * tig;
            float b0 = bias[col], b1 = bias[col + 1];
            *(float2*)(C + (size_t)row * N + col) =
                make_float2(acc[mi][ni][0] + b0, acc[mi][ni][1] + b1);
            *(float2*)(C + (size_t)(row + 8) * N + col) =
                make_float2(acc[mi][ni][2] + b0, acc[mi][ni][3] + b1);
        }
    }
}

// ===========================================================================
// Flash attention, fp32 (unchanged, known-good).
// ===========================================================================
__global__ __launch_bounds__(256) void flash_attn_kernel(
    const float* __restrict__ qkv, float* __restrict__ attn_out)
{
    __shared__ float Qs[64][65];
    __shared__ float Ks[32][65];
    __shared__ float Vs[32][65];
    __shared__ float Ps[64][33];

    const int tid = threadIdx.x;
    const int tx = tid & 15;
    const int ty = tid >> 4;
    const int h  = blockIdx.y;
    const int b  = blockIdx.z;
    const int n0 = blockIdx.x * 64;

    const float* base = qkv + (size_t)b * SEQ * QKVN + h * HD;

#pragma unroll
    for (int l = 0; l < 4; l++) {
        int id = tid + l * 256;
        int r  = id >> 4;
        int d4 = (id & 15) << 2;
        float4 q4 = *(const float4*)(base + (size_t)(n0 + r) * QKVN + d4);
        Qs[r][d4 + 0] = q4.x; Qs[r][d4 + 1] = q4.y;
        Qs[r][d4 + 2] = q4.z; Qs[r][d4 + 3] = q4.w;
    }

    float mrow[4], lrow[4], o[4][4];
#pragma unroll
    for (int i = 0; i < 4; i++) {
        mrow[i] = -1e30f;
        lrow[i] = 0.f;
#pragma unroll
        for (int ii = 0; ii < 4; ii++) o[i][ii] = 0.f;
    }
    const float scale = 0.125f;

    for (int t0 = 0; t0 < SEQ; t0 += 32) {
        __syncthreads();
#pragma unroll
        for (int l = 0; l < 2; l++) {
            int id = tid + l * 256;
            int r  = id >> 4;
            int d4 = (id & 15) << 2;
            float4 k4 = *(const float4*)(base + EMBED     + (size_t)(t0 + r) * QKVN + d4);
            float4 v4 = *(const float4*)(base + 2 * EMBED + (size_t)(t0 + r) * QKVN + d4);
            Ks[r][d4 + 0] = k4.x; Ks[r][d4 + 1] = k4.y;
            Ks[r][d4 + 2] = k4.z; Ks[r][d4 + 3] = k4.w;
            Vs[r][d4 + 0] = v4.x; Vs[r][d4 + 1] = v4.y;
            Vs[r][d4 + 2] = v4.z; Vs[r][d4 + 3] = v4.w;
        }
        __syncthreads();

        float s[4][2];
#pragma unroll
        for (int i = 0; i < 4; i++) { s[i][0] = 0.f; s[i][1] = 0.f; }
#pragma unroll 8
        for (int d = 0; d < 64; d++) {
            float rk0 = Ks[tx][d];
            float rk1 = Ks[tx + 16][d];
#pragma unroll
            for (int i = 0; i < 4; i++) {
                float rq = Qs[ty * 4 + i][d];
                s[i][0] = fmaf(rq, rk0, s[i][0]);
                s[i][1] = fmaf(rq, rk1, s[i][1]);
            }
        }

#pragma unroll
        for (int i = 0; i < 4; i++) {
            float s0 = s[i][0] * scale;
            float s1 = s[i][1] * scale;
            float smax = fmaxf(s0, s1);
#pragma unroll
            for (int msk = 8; msk >= 1; msk >>= 1)
                smax = fmaxf(smax, __shfl_xor_sync(0xffffffffu, smax, msk));
            float mnew = fmaxf(mrow[i], smax);
            float corr = __expf(mrow[i] - mnew);
            float p0 = __expf(s0 - mnew);
            float p1 = __expf(s1 - mnew);
            float ls = p0 + p1;
#pragma unroll
            for (int msk = 8; msk >= 1; msk >>= 1)
                ls += __shfl_xor_sync(0xffffffffu, ls, msk);
            lrow[i] = lrow[i] * corr + ls;
            mrow[i] = mnew;
#pragma unroll
            for (int ii = 0; ii < 4; ii++) o[i][ii] *= corr;
            Ps[ty * 4 + i][tx]      = p0;
            Ps[ty * 4 + i][tx + 16] = p1;
        }
        __syncthreads();

#pragma unroll 8
        for (int j = 0; j < 32; j++) {
            float rv[4];
#pragma unroll
            for (int ii = 0; ii < 4; ii++) rv[ii] = Vs[j][tx + 16 * ii];
#pragma unroll
            for (int i = 0; i < 4; i++) {
                float rp = Ps[ty * 4 + i][j];
#pragma unroll
                for (int ii = 0; ii < 4; ii++)
                    o[i][ii] = fmaf(rp, rv[ii], o[i][ii]);
            }
        }
    }

#pragma unroll
    for (int i = 0; i < 4; i++) {
        float inv = 1.f / lrow[i];
        size_t tok = (size_t)b * SEQ + n0 + ty * 4 + i;
#pragma unroll
        for (int ii = 0; ii < 4; ii++)
            attn_out[tok * EMBED + h * HD + tx + 16 * ii] = o[i][ii] * inv;
    }
}

// ===========================================================================
// Launch: transposes -> mma QKV GEMM -> flash attention -> mma out GEMM.
// Graph-capturable, allocation-free.
// ===========================================================================
extern "C" void kernel_launch(void* const* d_in, const int* in_sizes, int n_in,
                              void* d_out, int out_size)
{
    (void)in_sizes; (void)n_in; (void)out_size;
    const float* x     = (const float*)d_in[0];
    const float* w_qkv = (const float*)d_in[1];
    const float* b_qkv = (const float*)d_in[2];
    const float* w_out = (const float*)d_in[3];
    const float* b_out = (const float*)d_in[4];
    float* out = (float*)d_out;

    float *qkv = nullptr, *attn = nullptr, *wqkvT = nullptr, *woutT = nullptr;
    cudaGetSymbolAddress((void**)&qkv,   g_qkv);
    cudaGetSymbolAddress((void**)&attn,  g_attn);
    cudaGetSymbolAddress((void**)&wqkvT, g_wqkvT);
    cudaGetSymbolAddress((void**)&woutT, g_woutT);

    cudaFuncSetAttribute(mma_gemm_bias,
                         cudaFuncAttributeMaxDynamicSharedMemorySize, GEMM_SMEM_BYTES);

    // Weight transposes to K-major [N,K].
    transpose_kernel<<<dim3(QKVN / 32, EMBED / 32), dim3(32, 8)>>>(w_qkv, wqkvT, EMBED, QKVN);
    transpose_kernel<<<dim3(EMBED / 32, EMBED / 32), dim3(32, 8)>>>(w_out, woutT, EMBED, EMBED);

    // QKV projection: [4096,1024] @ [1024,3072] + b   (tf32 mma, 3x split)
    mma_gemm_bias<<<dim3(QKVN / 128, TOKENS / 128), 256, GEMM_SMEM_BYTES>>>(
        x, wqkvT, b_qkv, qkv, QKVN, EMBED);

    // Attention per (b, h, q-tile)
    flash_attn_kernel<<<dim3(SEQ / 64, NHEADS, BATCH), 256>>>(qkv, attn);

    // Output projection: [4096,1024] @ [1024,1024] + b
    mma_gemm_bias<<<dim3(EMBED / 128, TOKENS / 128), 256, GEMM_SMEM_BYTES>>>(
        attn, woutT, b_out, out, EMBED, EMBED);
}

// round 9
// speedup vs baseline: 1.5363x; 1.3157x over previous
#include <cuda_runtime.h>
#include <cstdint>
#include <math.h>

#define EMBED   1024
#define NHEADS  16
#define HD      64
#define SEQ     2048
#define BATCH   2
#define TOKENS  (BATCH * SEQ)      /* 4096 */
#define QKVN    (3 * EMBED)        /* 3072 */

// Scratch (no allocations allowed).
__device__ __align__(256) float g_qkv  [(size_t)TOKENS * QKVN];
__device__ __align__(256) float g_attn [(size_t)TOKENS * EMBED];
__device__ __align__(256) float g_wqkvT[(size_t)QKVN   * EMBED];
__device__ __align__(256) float g_woutT[(size_t)EMBED  * EMBED];

// ===========================================================================
// tf32 mma.sync helpers (baseline PTX, valid on compute_103 non-'a')
// ===========================================================================
__device__ __forceinline__ void mma_tf32(float* d, const uint32_t* a, const uint32_t* b) {
    asm volatile(
        "mma.sync.aligned.m16n8k8.row.col.f32.tf32.tf32.f32 "
        "{%0,%1,%2,%3}, {%4,%5,%6,%7}, {%8,%9}, {%0,%1,%2,%3};\n"
        : "+f"(d[0]), "+f"(d[1]), "+f"(d[2]), "+f"(d[3])
        : "r"(a[0]), "r"(a[1]), "r"(a[2]), "r"(a[3]), "r"(b[0]), "r"(b[1]));
}
__device__ __forceinline__ float tf32_hi(float x) {
    return __uint_as_float(__float_as_uint(x) & 0xFFFFE000u);
}
// Split a loaded fp32 into hi (tf32) + lo residue. HMMA truncates operand
// mantissas, so lo needs no explicit re-rounding.
__device__ __forceinline__ void split2(float x, uint32_t& hi, uint32_t& lo) {
    float h = tf32_hi(x);
    hi = __float_as_uint(h);
    lo = __float_as_uint(x - h);
}

// ===========================================================================
// Transpose: out[C][R] = in[R][C]  (32x32 tiles, block 32x8)
// ===========================================================================
__global__ __launch_bounds__(256) void transpose_kernel(
    const float* __restrict__ in, float* __restrict__ out, int R, int Ccols)
{
    __shared__ float t[32][33];
    int bx = blockIdx.x * 32, by = blockIdx.y * 32;
#pragma unroll
    for (int i = 0; i < 32; i += 8)
        t[threadIdx.y + i][threadIdx.x] =
            in[(size_t)(by + threadIdx.y + i) * Ccols + bx + threadIdx.x];
    __syncthreads();
#pragma unroll
    for (int i = 0; i < 32; i += 8)
        out[(size_t)(bx + threadIdx.y + i) * R + by + threadIdx.x] =
            t[threadIdx.x][threadIdx.y + i];
}

// ===========================================================================
// Tensor-core GEMM + bias (unchanged from R6, validated).
// ===========================================================================
#define LDT     36
#define TILE_F  (128 * LDT)
#define STAGE_F (4 * TILE_F)
#define GEMM_SMEM_BYTES (2 * STAGE_F * 4)

__global__ __launch_bounds__(256, 1)
void mma_gemm_bias(const float* __restrict__ A, const float* __restrict__ Bt,
                   const float* __restrict__ bias, float* __restrict__ C,
                   int N, int K)
{
    extern __shared__ float sm[];
    const int tid  = threadIdx.x;
    const int wid  = tid >> 5, lane = tid & 31;
    const int gid  = lane >> 2, tig = lane & 3;
    const int wm   = wid & 1, wn = wid >> 1;
    const int bm   = blockIdx.y * 128, bn = blockIdx.x * 128;

    float acc[4][4][4];
#pragma unroll
    for (int mi = 0; mi < 4; mi++)
#pragma unroll
        for (int ni = 0; ni < 4; ni++)
#pragma unroll
            for (int r = 0; r < 4; r++) acc[mi][ni][r] = 0.f;

    const float* Ag = A  + (size_t)bm * K;
    const float* Bg = Bt + (size_t)bn * K;

    int grow[4], gc4[4];
#pragma unroll
    for (int p = 0; p < 4; p++) {
        int id = tid + p * 256;
        grow[p] = id >> 3;
        gc4[p]  = (id & 7) << 2;
    }

    float4 pa[4], pb[4];
    auto gload = [&](int k0) {
#pragma unroll
        for (int p = 0; p < 4; p++) {
            pa[p] = *(const float4*)(Ag + (size_t)grow[p] * K + k0 + gc4[p]);
            pb[p] = *(const float4*)(Bg + (size_t)grow[p] * K + k0 + gc4[p]);
        }
    };
    auto sts = [&](int st) {
        float* base = sm + st * STAGE_F;
#pragma unroll
        for (int p = 0; p < 4; p++) {
            int off = grow[p] * LDT + gc4[p];
            float4 hi, lo;
            hi.x = tf32_hi(pa[p].x); lo.x = pa[p].x - hi.x;
            hi.y = tf32_hi(pa[p].y); lo.y = pa[p].y - hi.y;
            hi.z = tf32_hi(pa[p].z); lo.z = pa[p].z - hi.z;
            hi.w = tf32_hi(pa[p].w); lo.w = pa[p].w - hi.w;
            *(float4*)(base + off)          = hi;
            *(float4*)(base + TILE_F + off) = lo;
            hi.x = tf32_hi(pb[p].x); lo.x = pb[p].x - hi.x;
            hi.y = tf32_hi(pb[p].y); lo.y = pb[p].y - hi.y;
            hi.z = tf32_hi(pb[p].z); lo.z = pb[p].z - hi.z;
            hi.w = tf32_hi(pb[p].w); lo.w = pb[p].w - hi.w;
            *(float4*)(base + 2 * TILE_F + off) = hi;
            *(float4*)(base + 3 * TILE_F + off) = lo;
        }
    };
    auto compute = [&](int st) {
        const float* Ah = sm + st * STAGE_F;
        const float* Al = Ah + TILE_F;
        const float* Bh = Ah + 2 * TILE_F;
        const float* Bl = Ah + 3 * TILE_F;
#pragma unroll
        for (int ks = 0; ks < 4; ks++) {
            const int c0 = ks * 8 + tig;
            uint32_t ahf[4][4], alf[4][4];
#pragma unroll
            for (int mi = 0; mi < 4; mi++) {
                int r0 = (wm * 64 + mi * 16 + gid) * LDT;
                ahf[mi][0] = __float_as_uint(Ah[r0 + c0]);
                ahf[mi][1] = __float_as_uint(Ah[r0 + 8 * LDT + c0]);
                ahf[mi][2] = __float_as_uint(Ah[r0 + c0 + 4]);
                ahf[mi][3] = __float_as_uint(Ah[r0 + 8 * LDT + c0 + 4]);
                alf[mi][0] = __float_as_uint(Al[r0 + c0]);
                alf[mi][1] = __float_as_uint(Al[r0 + 8 * LDT + c0]);
                alf[mi][2] = __float_as_uint(Al[r0 + c0 + 4]);
                alf[mi][3] = __float_as_uint(Al[r0 + 8 * LDT + c0 + 4]);
            }
            uint32_t bhf[4][2], blf[4][2];
#pragma unroll
            for (int ni = 0; ni < 4; ni++) {
                int n0 = (wn * 32 + ni * 8 + gid) * LDT;
                bhf[ni][0] = __float_as_uint(Bh[n0 + c0]);
                bhf[ni][1] = __float_as_uint(Bh[n0 + c0 + 4]);
                blf[ni][0] = __float_as_uint(Bl[n0 + c0]);
                blf[ni][1] = __float_as_uint(Bl[n0 + c0 + 4]);
            }
#pragma unroll
            for (int mi = 0; mi < 4; mi++)
#pragma unroll
                for (int ni = 0; ni < 4; ni++) {
                    mma_tf32(acc[mi][ni], ahf[mi], bhf[ni]);
                    mma_tf32(acc[mi][ni], ahf[mi], blf[ni]);
                    mma_tf32(acc[mi][ni], alf[mi], bhf[ni]);
                }
        }
    };

    const int NCH = K >> 5;
    gload(0);
    sts(0);
    __syncthreads();
    for (int c = 0; c < NCH; c++) {
        const int st = c & 1;
        if (c + 1 < NCH) gload((c + 1) * 32);
        compute(st);
        __syncthreads();
        if (c + 1 < NCH) {
            sts(st ^ 1);
            __syncthreads();
        }
    }

#pragma unroll
    for (int mi = 0; mi < 4; mi++) {
        int row = bm + wm * 64 + mi * 16 + gid;
#pragma unroll
        for (int ni = 0; ni < 4; ni++) {
            int col = bn + wn * 32 + ni * 8 + 2 * tig;
            float b0 = bias[col], b1 = bias[col + 1];
            *(float2*)(C + (size_t)row * N + col) =
                make_float2(acc[mi][ni][0] + b0, acc[mi][ni][1] + b1);
            *(float2*)(C + (size_t)(row + 8) * N + col) =
                make_float2(acc[mi][ni][2] + b0, acc[mi][ni][3] + b1);
        }
    }
}

// ===========================================================================
// Flash attention on tensor cores (mma.sync tf32, 3x split).
// CTA: 128 q-rows, 8 warps, warp tile = 16 q-rows x full 64 kv columns
// -> softmax rows are warp-local (shfl-only reductions, P warp-private).
// KV tiles of 64. V stored transposed (Vt[d][kv]) at load.
// Smem stride 68 -> conflict-free fragment gathers (bank = 4*gid+tig).
// Smem: Q[128*68] + K[64*68] + Vt[64*68] + P[128*68] = 104448 B dynamic.
// ===========================================================================
#define FLD 68
#define FA_SMEM_F (128*FLD + 64*FLD + 64*FLD + 128*FLD)
#define FA_SMEM_BYTES (FA_SMEM_F * 4)

__global__ __launch_bounds__(256, 1)
void flash_mma_kernel(const float* __restrict__ qkv, float* __restrict__ attn_out)
{
    extern __shared__ float fs[];
    float* Qs = fs;
    float* Ks = Qs + 128 * FLD;
    float* Vt = Ks + 64 * FLD;
    float* Ps = Vt + 64 * FLD;

    const int tid  = threadIdx.x;
    const int wid  = tid >> 5, lane = tid & 31;
    const int gid  = lane >> 2, tig = lane & 3;
    const int h  = blockIdx.y;
    const int b  = blockIdx.z;
    const int n0 = blockIdx.x * 128;

    const float* base = qkv + (size_t)b * SEQ * QKVN + h * HD;

    // Load Q tile 128x64 into smem (fp32; split at fragment load).
#pragma unroll
    for (int l = 0; l < 8; l++) {
        int id = tid + l * 256;         // 0..2047
        int r  = id >> 4;               // 0..127
        int d4 = (id & 15) << 2;        // 0..60
        float4 q4 = *(const float4*)(base + (size_t)(n0 + r) * QKVN + d4);
        *(float4*)(Qs + r * FLD + d4) = q4;
    }

    float oacc[8][4];
#pragma unroll
    for (int n = 0; n < 8; n++)
#pragma unroll
        for (int r = 0; r < 4; r++) oacc[n][r] = 0.f;
    float m0 = -1e30f, m1 = -1e30f, l0 = 0.f, l1 = 0.f;
    const float scale = 0.125f;

    const float* Aq = Qs + wid * 16 * FLD;
    float* Pw = Ps + wid * 16 * FLD;

    for (int t0 = 0; t0 < SEQ; t0 += 64) {
        __syncthreads();   // all warps done reading K/Vt of prev tile
        // Load K tile (rows) and V tile (transposed).
#pragma unroll
        for (int l = 0; l < 4; l++) {
            int id = tid + l * 256;     // 0..1023
            int r  = id >> 4;           // 0..63
            int d4 = (id & 15) << 2;
            float4 k4 = *(const float4*)(base + EMBED     + (size_t)(t0 + r) * QKVN + d4);
            *(float4*)(Ks + r * FLD + d4) = k4;
            float4 v4 = *(const float4*)(base + 2 * EMBED + (size_t)(t0 + r) * QKVN + d4);
            Vt[(d4 + 0) * FLD + r] = v4.x;
            Vt[(d4 + 1) * FLD + r] = v4.y;
            Vt[(d4 + 2) * FLD + r] = v4.z;
            Vt[(d4 + 3) * FLD + r] = v4.w;
        }
        __syncthreads();

        // ---- S = Q @ K^T (16x64 per warp), 3x tf32 split ----
        float sacc[8][4];
#pragma unroll
        for (int n = 0; n < 8; n++)
#pragma unroll
            for (int r = 0; r < 4; r++) sacc[n][r] = 0.f;

#pragma unroll
        for (int ks = 0; ks < 8; ks++) {
            const int c0 = ks * 8 + tig;
            uint32_t ah[4], al[4];
            split2(Aq[gid * FLD + c0],           ah[0], al[0]);
            split2(Aq[(gid + 8) * FLD + c0],     ah[1], al[1]);
            split2(Aq[gid * FLD + c0 + 4],       ah[2], al[2]);
            split2(Aq[(gid + 8) * FLD + c0 + 4], ah[3], al[3]);
#pragma unroll
            for (int n = 0; n < 8; n++) {
                uint32_t bh[2], bl[2];
                split2(Ks[(n * 8 + gid) * FLD + c0],     bh[0], bl[0]);
                split2(Ks[(n * 8 + gid) * FLD + c0 + 4], bh[1], bl[1]);
                mma_tf32(sacc[n], ah, bh);
                mma_tf32(sacc[n], ah, bl);
                mma_tf32(sacc[n], al, bh);
            }
        }

        // ---- online softmax (rows gid and gid+8 of warp tile) ----
        float rmax0 = -1e30f, rmax1 = -1e30f;
#pragma unroll
        for (int n = 0; n < 8; n++) {
            rmax0 = fmaxf(rmax0, fmaxf(sacc[n][0], sacc[n][1]));
            rmax1 = fmaxf(rmax1, fmaxf(sacc[n][2], sacc[n][3]));
        }
        rmax0 = fmaxf(rmax0, __shfl_xor_sync(0xffffffffu, rmax0, 1));
        rmax0 = fmaxf(rmax0, __shfl_xor_sync(0xffffffffu, rmax0, 2));
        rmax1 = fmaxf(rmax1, __shfl_xor_sync(0xffffffffu, rmax1, 1));
        rmax1 = fmaxf(rmax1, __shfl_xor_sync(0xffffffffu, rmax1, 2));

        float mn0 = fmaxf(m0, rmax0 * scale);
        float mn1 = fmaxf(m1, rmax1 * scale);
        float corr0 = __expf(m0 - mn0);
        float corr1 = __expf(m1 - mn1);
        float ls0 = 0.f, ls1 = 0.f;
#pragma unroll
        for (int n = 0; n < 8; n++) {
            float p0 = __expf(sacc[n][0] * scale - mn0);
            float p1 = __expf(sacc[n][1] * scale - mn0);
            float p2 = __expf(sacc[n][2] * scale - mn1);
            float p3 = __expf(sacc[n][3] * scale - mn1);
            ls0 += p0 + p1;
            ls1 += p2 + p3;
            *(float2*)(Pw + gid * FLD + n * 8 + 2 * tig)       = make_float2(p0, p1);
            *(float2*)(Pw + (gid + 8) * FLD + n * 8 + 2 * tig) = make_float2(p2, p3);
        }
        ls0 += __shfl_xor_sync(0xffffffffu, ls0, 1);
        ls0 += __shfl_xor_sync(0xffffffffu, ls0, 2);
        ls1 += __shfl_xor_sync(0xffffffffu, ls1, 1);
        ls1 += __shfl_xor_sync(0xffffffffu, ls1, 2);
        l0 = l0 * corr0 + ls0;  m0 = mn0;
        l1 = l1 * corr1 + ls1;  m1 = mn1;
#pragma unroll
        for (int n = 0; n < 8; n++) {
            oacc[n][0] *= corr0; oacc[n][1] *= corr0;
            oacc[n][2] *= corr1; oacc[n][3] *= corr1;
        }
        __syncwarp();   // P is warp-private: warp-level ordering suffices

        // ---- O += P @ V (Vt[d][kv]), 3x split ----
#pragma unroll
        for (int ks = 0; ks < 8; ks++) {
            const int c0 = ks * 8 + tig;
            uint32_t ah[4], al[4];
            split2(Pw[gid * FLD + c0],           ah[0], al[0]);
            split2(Pw[(gid + 8) * FLD + c0],     ah[1], al[1]);
            split2(Pw[gid * FLD + c0 + 4],       ah[2], al[2]);
            split2(Pw[(gid + 8) * FLD + c0 + 4], ah[3], al[3]);
#pragma unroll
            for (int n = 0; n < 8; n++) {
                uint32_t bh[2], bl[2];
                split2(Vt[(n * 8 + gid) * FLD + c0],     bh[0], bl[0]);
                split2(Vt[(n * 8 + gid) * FLD + c0 + 4], bh[1], bl[1]);
                mma_tf32(oacc[n], ah, bh);
                mma_tf32(oacc[n], ah, bl);
                mma_tf32(oacc[n], al, bh);
            }
        }
    }

    // Epilogue: normalize and write token-major.
    float inv0 = 1.f / l0, inv1 = 1.f / l1;
    size_t tok0 = (size_t)b * SEQ + n0 + wid * 16 + gid;
    size_t tok1 = tok0 + 8;
#pragma unroll
    for (int n = 0; n < 8; n++) {
        int col = h * HD + n * 8 + 2 * tig;
        *(float2*)(attn_out + tok0 * EMBED + col) =
            make_float2(oacc[n][0] * inv0, oacc[n][1] * inv0);
        *(float2*)(attn_out + tok1 * EMBED + col) =
            make_float2(oacc[n][2] * inv1, oacc[n][3] * inv1);
    }
}

// ===========================================================================
// Launch: transposes -> mma QKV GEMM -> mma flash attention -> mma out GEMM.
// Graph-capturable, allocation-free.
// ===========================================================================
extern "C" void kernel_launch(void* const* d_in, const int* in_sizes, int n_in,
                              void* d_out, int out_size)
{
    (void)in_sizes; (void)n_in; (void)out_size;
    const float* x     = (const float*)d_in[0];
    const float* w_qkv = (const float*)d_in[1];
    const float* b_qkv = (const float*)d_in[2];
    const float* w_out = (const float*)d_in[3];
    const float* b_out = (const float*)d_in[4];
    float* out = (float*)d_out;

    float *qkv = nullptr, *attn = nullptr, *wqkvT = nullptr, *woutT = nullptr;
    cudaGetSymbolAddress((void**)&qkv,   g_qkv);
    cudaGetSymbolAddress((void**)&attn,  g_attn);
    cudaGetSymbolAddress((void**)&wqkvT, g_wqkvT);
    cudaGetSymbolAddress((void**)&woutT, g_woutT);

    cudaFuncSetAttribute(mma_gemm_bias,
                         cudaFuncAttributeMaxDynamicSharedMemorySize, GEMM_SMEM_BYTES);
    cudaFuncSetAttribute(flash_mma_kernel,
                         cudaFuncAttributeMaxDynamicSharedMemorySize, FA_SMEM_BYTES);

    transpose_kernel<<<dim3(QKVN / 32, EMBED / 32), dim3(32, 8)>>>(w_qkv, wqkvT, EMBED, QKVN);
    transpose_kernel<<<dim3(EMBED / 32, EMBED / 32), dim3(32, 8)>>>(w_out, woutT, EMBED, EMBED);

    mma_gemm_bias<<<dim3(QKVN / 128, TOKENS / 128), 256, GEMM_SMEM_BYTES>>>(
        x, wqkvT, b_qkv, qkv, QKVN, EMBED);

    flash_mma_kernel<<<dim3(SEQ / 128, NHEADS, BATCH), 256, FA_SMEM_BYTES>>>(qkv, attn);

    mma_gemm_bias<<<dim3(EMBED / 128, TOKENS / 128), 256, GEMM_SMEM_BYTES>>>(
        attn, woutT, b_out, out, EMBED, EMBED);
}